// round 4
// baseline (speedup 1.0000x reference)
#include <cuda_runtime.h>
#include <cuda_bf16.h>
#include <math.h>

#define NN 50000
#define NF 128
#define DIM 10
#define NE 1600000
#define NG 1000
#define PD 12            // padded feature stride (10 -> 12, 3x float4)

// ---------------- scratch (no allocations allowed) ----------------
__device__ int    g_src[NE];
__device__ int    g_dst[NE];
__device__ int    g_csr[NE];        // src ids grouped by dst
__device__ int    g_deg[NN];
__device__ int    g_row[NN + 1];    // CSR row starts
__device__ int    g_cur[NN];        // scatter cursors
__device__ float  g_deginv[NN];
__device__ float4 g_xl[NN * 3];
__device__ float4 g_xr[NN * 3];
__device__ float4 g_hl[NN * 3];
__device__ float4 g_hr[NN * 3];
__device__ float4 g_pool[NG * 3];
__device__ int    g_cnt[NG];
__device__ int    g_ei32;   // 1 if edge_index arrived as int32
__device__ int    g_b32;    // 1 if batch arrived as int32

__device__ __forceinline__ void red4(float4* p, float4 v) {
    asm volatile("red.global.add.v4.f32 [%0], {%1,%2,%3,%4};"
                 :: "l"(p), "f"(v.x), "f"(v.y), "f"(v.z), "f"(v.w) : "memory");
}

// ---------------- kernels ----------------
// Zero deg/pool/cnt; thread (0,0) also performs dtype detection.
__global__ void init_k(const long long* ei, const long long* batch) {
    int i = blockIdx.x * blockDim.x + threadIdx.x;
    int stride = gridDim.x * blockDim.x;
    float4 z = make_float4(0.f, 0.f, 0.f, 0.f);
    for (int j = i; j < NN; j += stride) g_deg[j] = 0;
    for (int j = i; j < NG * 3; j += stride) g_pool[j] = z;
    for (int j = i; j < NG; j += stride) g_cnt[j] = 0;
    if (i == 0) {
        int f = 0;
        for (int k = 0; k < 64; k++) {
            long long v = ei[k];
            if (v < 0 || v >= NN) f = 1;
        }
        g_ei32 = f;
        int fb = 0;
        for (int k = 0; k < 64; k++) {
            long long v = batch[12000 + k];
            if (v < 0 || v >= NG) fb = 1;
        }
        g_b32 = fb;
    }
}

__global__ void prep_edges(const long long* ei) {
    int e = blockIdx.x * blockDim.x + threadIdx.x;
    if (e >= NE) return;
    int s, d;
    if (g_ei32) {
        const int* e32 = (const int*)ei;
        s = e32[e]; d = e32[NE + e];
    } else {
        s = (int)ei[e]; d = (int)ei[NE + e];
    }
    g_src[e] = s;
    g_dst[e] = d;
    atomicAdd(&g_deg[d], 1);
}

// Single-block exclusive scan of deg -> row starts + cursors + deginv.
__global__ __launch_bounds__(1024) void scan_deg() {
    __shared__ int sh[1024];
    int t = threadIdx.x;
    const int PER = (NN + 1023) / 1024;   // 49
    int base = t * PER;
    int sum = 0;
    for (int i = 0; i < PER; i++) {
        int idx = base + i;
        if (idx < NN) sum += g_deg[idx];
    }
    sh[t] = sum;
    __syncthreads();
    for (int off = 1; off < 1024; off <<= 1) {
        int v = (t >= off) ? sh[t - off] : 0;
        __syncthreads();
        sh[t] += v;
        __syncthreads();
    }
    int running = sh[t] - sum;   // exclusive prefix
    for (int i = 0; i < PER; i++) {
        int idx = base + i;
        if (idx < NN) {
            g_row[idx] = running;
            g_cur[idx] = running;
            int dg = g_deg[idx];
            g_deginv[idx] = 1.0f / fmaxf((float)dg, 1.0f);
            running += dg;
        }
    }
    if (t == 0) g_row[NN] = NE;
}

// Counting-sort scatter: group src ids by destination node.
__global__ void scatter_csr() {
    int e = blockIdx.x * blockDim.x + threadIdx.x;
    if (e >= NE) return;
    int d = g_dst[e];
    int pos = atomicAdd(&g_cur[d], 1);
    g_csr[pos] = g_src[e];
}

// Fused GEMV: xl = x @ W1_l^T, xr = x @ W1_r^T
__global__ __launch_bounds__(256) void gemv1(const float* __restrict__ x,
                                             const float* __restrict__ W1l,
                                             const float* __restrict__ W1r) {
    __shared__ __align__(16) float sW[20 * 128];
    __shared__ __align__(16) float sX[64 * 132];
    int t = threadIdx.x;
    for (int i = t; i < 20 * 128; i += 256) {
        int d = i >> 7, k = i & 127;
        sW[i] = (d < 10) ? W1l[d * 128 + k] : W1r[(d - 10) * 128 + k];
    }
    int n0 = blockIdx.x * 64;
    for (int i = t; i < 64 * 32; i += 256) {
        int n = i >> 5, k4 = i & 31;
        int node = n0 + n;
        float4 v = (node < NN) ? ((const float4*)x)[node * 32 + k4]
                               : make_float4(0.f, 0.f, 0.f, 0.f);
        *(float4*)&sX[n * 132 + k4 * 4] = v;
    }
    __syncthreads();
    int n = t & 63, g = t >> 6;
    int node = n0 + n;
    float acc[5] = {0.f, 0.f, 0.f, 0.f, 0.f};
    const float4* xr4 = (const float4*)&sX[n * 132];
    const float4* w4  = (const float4*)sW;
#pragma unroll
    for (int k4 = 0; k4 < 32; k4++) {
        float4 xv = xr4[k4];
#pragma unroll
        for (int j = 0; j < 5; j++) {
            float4 w = w4[(g * 5 + j) * 32 + k4];
            acc[j] += xv.x * w.x + xv.y * w.y + xv.z * w.z + xv.w * w.w;
        }
    }
    if (node < NN) {
#pragma unroll
        for (int j = 0; j < 5; j++) {
            int d = g * 5 + j;
            float* dst = (d < 10) ? (float*)g_xl : (float*)g_xr;
            int dd = (d < 10) ? d : d - 10;
            dst[node * PD + dd] = acc[j];
        }
    }
}

// Layer 1: thread-per-node segment sum over CSR + relu + two 10x10 GEMVs.
__global__ __launch_bounds__(256) void agg1_combine(const float* __restrict__ W2l,
                                                    const float* __restrict__ W2r) {
    __shared__ float sWl[100], sWr[100];
    int t = threadIdx.x;
    if (t < 100) { sWl[t] = W2l[t]; sWr[t] = W2r[t]; }
    __syncthreads();
    int n = blockIdx.x * blockDim.x + t;
    if (n >= NN) return;
    int b0 = g_row[n], b1 = g_row[n + 1];
    float4 a0 = make_float4(0.f,0.f,0.f,0.f), a1 = a0, a2 = a0;
    int e = b0;
    for (; e + 1 < b1; e += 2) {
        int s0 = g_csr[e], s1 = g_csr[e + 1];
        const float4* f0 = &g_xl[s0 * 3];
        const float4* f1 = &g_xl[s1 * 3];
        float4 p0 = f0[0], p1 = f0[1], p2 = f0[2];
        float4 q0 = f1[0], q1 = f1[1], q2 = f1[2];
        a0.x += p0.x + q0.x; a0.y += p0.y + q0.y; a0.z += p0.z + q0.z; a0.w += p0.w + q0.w;
        a1.x += p1.x + q1.x; a1.y += p1.y + q1.y; a1.z += p1.z + q1.z; a1.w += p1.w + q1.w;
        a2.x += p2.x + q2.x; a2.y += p2.y + q2.y; a2.z += p2.z + q2.z; a2.w += p2.w + q2.w;
    }
    if (e < b1) {
        int s0 = g_csr[e];
        const float4* f0 = &g_xl[s0 * 3];
        float4 p0 = f0[0], p1 = f0[1], p2 = f0[2];
        a0.x += p0.x; a0.y += p0.y; a0.z += p0.z; a0.w += p0.w;
        a1.x += p1.x; a1.y += p1.y; a1.z += p1.z; a1.w += p1.w;
        a2.x += p2.x; a2.y += p2.y; a2.z += p2.z; a2.w += p2.w;
    }
    float di = g_deginv[n];
    const float* xr = (const float*)g_xr + n * PD;
    float agg[12];
    *(float4*)&agg[0] = a0; *(float4*)&agg[4] = a1; *(float4*)&agg[8] = a2;
    float h[10];
#pragma unroll
    for (int d = 0; d < 10; d++) h[d] = fmaxf(agg[d] * di + xr[d], 0.f);
    float hl[12], hr[12];
#pragma unroll
    for (int d = 0; d < 10; d++) {
        float al = 0.f, ar = 0.f;
#pragma unroll
        for (int j = 0; j < 10; j++) {
            al += sWl[d * 10 + j] * h[j];
            ar += sWr[d * 10 + j] * h[j];
        }
        hl[d] = al; hr[d] = ar;
    }
    hl[10] = hl[11] = 0.f; hr[10] = hr[11] = 0.f;
    float4* pl = &g_hl[n * 3];
    float4* pr = &g_hr[n * 3];
#pragma unroll
    for (int q = 0; q < 3; q++) {
        pl[q] = make_float4(hl[q*4], hl[q*4+1], hl[q*4+2], hl[q*4+3]);
        pr[q] = make_float4(hr[q*4], hr[q*4+1], hr[q*4+2], hr[q*4+3]);
    }
}

// Layer 2 + global mean pool: segment sum over CSR (g_hl), combine with g_hr,
// then vector-reduce into per-graph pool and count nodes per graph.
__global__ __launch_bounds__(256) void agg2_pool(const long long* __restrict__ batch) {
    int n = blockIdx.x * blockDim.x + threadIdx.x;
    if (n >= NN) return;
    int b0 = g_row[n], b1 = g_row[n + 1];
    float4 a0 = make_float4(0.f,0.f,0.f,0.f), a1 = a0, a2 = a0;
    int e = b0;
    for (; e + 1 < b1; e += 2) {
        int s0 = g_csr[e], s1 = g_csr[e + 1];
        const float4* f0 = &g_hl[s0 * 3];
        const float4* f1 = &g_hl[s1 * 3];
        float4 p0 = f0[0], p1 = f0[1], p2 = f0[2];
        float4 q0 = f1[0], q1 = f1[1], q2 = f1[2];
        a0.x += p0.x + q0.x; a0.y += p0.y + q0.y; a0.z += p0.z + q0.z; a0.w += p0.w + q0.w;
        a1.x += p1.x + q1.x; a1.y += p1.y + q1.y; a1.z += p1.z + q1.z; a1.w += p1.w + q1.w;
        a2.x += p2.x + q2.x; a2.y += p2.y + q2.y; a2.z += p2.z + q2.z; a2.w += p2.w + q2.w;
    }
    if (e < b1) {
        int s0 = g_csr[e];
        const float4* f0 = &g_hl[s0 * 3];
        float4 p0 = f0[0], p1 = f0[1], p2 = f0[2];
        a0.x += p0.x; a0.y += p0.y; a0.z += p0.z; a0.w += p0.w;
        a1.x += p1.x; a1.y += p1.y; a1.z += p1.z; a1.w += p1.w;
        a2.x += p2.x; a2.y += p2.y; a2.z += p2.z; a2.w += p2.w;
    }
    float di = g_deginv[n];
    const float4* hr = &g_hr[n * 3];
    float4 h0 = hr[0], h1 = hr[1], h2 = hr[2];
    a0.x = a0.x * di + h0.x; a0.y = a0.y * di + h0.y; a0.z = a0.z * di + h0.z; a0.w = a0.w * di + h0.w;
    a1.x = a1.x * di + h1.x; a1.y = a1.y * di + h1.y; a1.z = a1.z * di + h1.z; a1.w = a1.w * di + h1.w;
    a2.x = a2.x * di + h2.x; a2.y = a2.y * di + h2.y;
    a2.z = 0.f; a2.w = 0.f;   // padding lanes must not pollute pool
    int b = g_b32 ? ((const int*)batch)[n] : (int)batch[n];
    float4* pp = &g_pool[b * 3];
    red4(&pp[0], a0);
    red4(&pp[1], a1);
    red4(&pp[2], a2);
    atomicAdd(&g_cnt[b], 1);
}

__global__ void final_out(const float* __restrict__ Wfc, float* __restrict__ out) {
    int g = blockIdx.x * blockDim.x + threadIdx.x;
    if (g >= NG) return;
    float c = fmaxf((float)g_cnt[g], 1.0f);
    const float* p = (const float*)g_pool + g * PD;
    float z = 0.f;
#pragma unroll
    for (int d = 0; d < 10; d++) z += p[d] * Wfc[d];
    z /= c;
    out[g] = 1.0f / (1.0f + expf(-z));
}

// ---------------- launch ----------------
extern "C" void kernel_launch(void* const* d_in, const int* in_sizes, int n_in,
                              void* d_out, int out_size) {
    const float *x = 0, *W1l = 0, *W1r = 0, *W2l = 0, *W2r = 0, *Wfc = 0;
    const long long *ei = 0, *batch = 0;
    for (int i = 0; i < n_in; i++) {
        int sz = in_sizes[i];
        if (sz == NN * NF)        x = (const float*)d_in[i];
        else if (sz == DIM * NF)  { if (!W1l) W1l = (const float*)d_in[i]; else W1r = (const float*)d_in[i]; }
        else if (sz == DIM * DIM) { if (!W2l) W2l = (const float*)d_in[i]; else W2r = (const float*)d_in[i]; }
        else if (sz == DIM)       Wfc = (const float*)d_in[i];
        else if (sz == 2 * NE)    ei = (const long long*)d_in[i];
        else if (sz == NN)        batch = (const long long*)d_in[i];
    }
    float* out = (float*)d_out;

    const int TB = 256;
    init_k<<<32, TB>>>(ei, batch);
    prep_edges<<<(NE + TB - 1) / TB, TB>>>(ei);
    scan_deg<<<1, 1024>>>();
    scatter_csr<<<(NE + TB - 1) / TB, TB>>>();
    gemv1<<<(NN + 63) / 64, TB>>>(x, W1l, W1r);
    agg1_combine<<<(NN + TB - 1) / TB, TB>>>(W2l, W2r);
    agg2_pool<<<(NN + TB - 1) / TB, TB>>>(batch);
    final_out<<<(NG + TB - 1) / TB, TB>>>(Wfc, out);
}